// round 1
// baseline (speedup 1.0000x reference)
#include <cuda_runtime.h>
#include <math.h>

#define Gn 8
#define Hn 64
#define In 64
#define Bn 32
#define Tn 1000
#define ROWS (Bn * Tn)   // 32000

// Scratch: xp[((t*B + b)*G + g)*192 + j]  (input projections incl. bih)
__device__ float g_xp[(size_t)ROWS * Gn * 192];

// ---------------------------------------------------------------------------
// Phase 1: xp = x @ Wih^T + bih   (per group; 64-row x 64-col tiles)
// grid = (500 row-tiles, 8 groups, 3 gate-sections), block = 256
// ---------------------------------------------------------------------------
__global__ void __launch_bounds__(256) xproj_kernel(const float* __restrict__ x,
                                                    const float* __restrict__ Wih,
                                                    const float* __restrict__ bih)
{
    __shared__ __align__(16) float xs[64][68];  // [k][row]
    __shared__ __align__(16) float ws[64][68];  // [k][col]

    const int tile = blockIdx.x;   // row tile (64 rows of B*T)
    const int g    = blockIdx.y;   // group
    const int sec  = blockIdx.z;   // gate section: 0=r,1=z,2=n (64 cols each)
    const int tid  = threadIdx.x;

    // Load x tile transposed: xs[k][row]. Global reads coalesced along k.
    for (int idx = tid; idx < 64 * 64; idx += 256) {
        int row = idx >> 6;
        int k   = idx & 63;
        int n   = tile * 64 + row;              // n = b*T + t
        xs[k][row] = x[(size_t)n * (Gn * In) + g * In + k];
    }
    // Load Wih section transposed: ws[k][j]
    for (int idx = tid; idx < 64 * 64; idx += 256) {
        int j = idx >> 6;
        int k = idx & 63;
        ws[k][j] = Wih[((size_t)g * 192 + sec * 64 + j) * In + k];
    }
    __syncthreads();

    const int tx = tid & 15;
    const int ty = tid >> 4;
    const int r0 = ty * 4;
    const int c0 = tx * 4;

    float acc[4][4];
#pragma unroll
    for (int i = 0; i < 4; i++)
#pragma unroll
        for (int c = 0; c < 4; c++) acc[i][c] = 0.f;

#pragma unroll 16
    for (int k = 0; k < 64; k++) {
        float4 av = *(const float4*)&xs[k][r0];
        float4 wv = *(const float4*)&ws[k][c0];
        acc[0][0] += av.x * wv.x; acc[0][1] += av.x * wv.y; acc[0][2] += av.x * wv.z; acc[0][3] += av.x * wv.w;
        acc[1][0] += av.y * wv.x; acc[1][1] += av.y * wv.y; acc[1][2] += av.y * wv.z; acc[1][3] += av.y * wv.w;
        acc[2][0] += av.z * wv.x; acc[2][1] += av.z * wv.y; acc[2][2] += av.z * wv.z; acc[2][3] += av.z * wv.w;
        acc[3][0] += av.w * wv.x; acc[3][1] += av.w * wv.y; acc[3][2] += av.w * wv.z; acc[3][3] += av.w * wv.w;
    }

    // bias + store to xp in [t][b][g][192] layout
    float4 bv = *(const float4*)&bih[g * 192 + sec * 64 + c0];
#pragma unroll
    for (int i = 0; i < 4; i++) {
        int n = tile * 64 + r0 + i;
        int b = n / Tn;
        int t = n - b * Tn;
        size_t o = ((size_t)(t * Bn + b) * Gn + g) * 192 + sec * 64 + c0;
        float4 v;
        v.x = acc[i][0] + bv.x;
        v.y = acc[i][1] + bv.y;
        v.z = acc[i][2] + bv.z;
        v.w = acc[i][3] + bv.w;
        *(float4*)&g_xp[o] = v;
    }
}

// ---------------------------------------------------------------------------
// Phase 2: sequential scan. One block per (b, g). 192 threads: thread j owns
// gate-row j of Whh (64 floats in registers). h lives in smem.
// grid = (32, 8), block = 192
// ---------------------------------------------------------------------------
__global__ void __launch_bounds__(192) scan_kernel(const float* __restrict__ h0,
                                                   const float* __restrict__ Whh,
                                                   const float* __restrict__ bhh,
                                                   float* __restrict__ out)
{
    const int b = blockIdx.x;
    const int g = blockIdx.y;
    const int j = threadIdx.x;  // 0..191

    __shared__ __align__(16) float h_sh[64];
    __shared__ __align__(16) float gh_sh[192];
    __shared__ __align__(16) float xq_sh[192];

    // Whh row j -> registers (16 x float4)
    float4 w[16];
    const float4* wrow = (const float4*)&Whh[((size_t)g * 192 + j) * Hn];
#pragma unroll
    for (int q = 0; q < 16; q++) w[q] = wrow[q];
    const float bj = bhh[g * 192 + j];

    if (j < 64) h_sh[j] = h0[((size_t)g * Bn + b) * Hn + j];

    const float* xp_col = &g_xp[((size_t)b * Gn + g) * 192 + j];
    float* out_row = out + (size_t)b * Tn * (Gn * Hn) + g * Hn;
    const size_t xp_tstride = (size_t)Bn * Gn * 192;

    for (int t = 0; t < Tn; t++) {
        // issue the xp load early; consumed only after the 64-FMA dot
        float xv = xp_col[(size_t)t * xp_tstride];

        __syncthreads();   // h_sh ready (init or previous step's update)

        float acc = bj;
        const float4* h4 = (const float4*)h_sh;
#pragma unroll
        for (int q = 0; q < 16; q++) {
            float4 hv = h4[q];
            acc += w[q].x * hv.x;
            acc += w[q].y * hv.y;
            acc += w[q].z * hv.z;
            acc += w[q].w * hv.w;
        }
        gh_sh[j] = acc;
        xq_sh[j] = xv;
        __syncthreads();

        if (j < 64) {
            float r  = 1.f / (1.f + expf(-(xq_sh[j]       + gh_sh[j])));
            float z  = 1.f / (1.f + expf(-(xq_sh[64 + j]  + gh_sh[64 + j])));
            float nn = tanhf(xq_sh[128 + j] + r * gh_sh[128 + j]);
            float hn = (1.f - z) * nn + z * h_sh[j];
            h_sh[j] = hn;
            out_row[(size_t)t * (Gn * Hn) + j] = hn;
        }
    }

    __syncthreads();
    if (j < 64) {
        // final hidden state, laid out [G, B, H] after the main output
        out[(size_t)Bn * Tn * (Gn * Hn) + ((size_t)g * Bn + b) * Hn + j] = h_sh[j];
    }
}

// ---------------------------------------------------------------------------
extern "C" void kernel_launch(void* const* d_in, const int* in_sizes, int n_in,
                              void* d_out, int out_size)
{
    const float* x   = (const float*)d_in[0];
    const float* h0  = (const float*)d_in[1];
    const float* Wih = (const float*)d_in[2];
    const float* Whh = (const float*)d_in[3];
    const float* bih = (const float*)d_in[4];
    const float* bhh = (const float*)d_in[5];
    float* out = (float*)d_out;

    dim3 g1(ROWS / 64, Gn, 3);
    xproj_kernel<<<g1, 256>>>(x, Wih, bih);

    dim3 g2(Bn, Gn);
    scan_kernel<<<g2, 192>>>(h0, Whh, bhh, out);
}

// round 2
// speedup vs baseline: 1.4196x; 1.4196x over previous
#include <cuda_runtime.h>
#include <math.h>
#include <stdint.h>

#define Gn 8
#define Hn 64
#define In 64
#define Bn 32
#define Tn 1000
#define ROWS (Bn * Tn)   // 32000

// Scratch: xp[((b*G+g)*T + t)*192 + j]  — sequential in t per (b,g) block
__device__ float g_xp[(size_t)Bn * Gn * Tn * 192];

// ---------------- packed f32x2 helpers (sm_103a) ----------------
__device__ __forceinline__ uint64_t ffma2(uint64_t a, uint64_t b, uint64_t c) {
    uint64_t d;
    asm("fma.rn.f32x2 %0, %1, %2, %3;" : "=l"(d) : "l"(a), "l"(b), "l"(c));
    return d;
}
__device__ __forceinline__ uint64_t fadd2(uint64_t a, uint64_t b) {
    uint64_t d;
    asm("add.rn.f32x2 %0, %1, %2;" : "=l"(d) : "l"(a), "l"(b));
    return d;
}
__device__ __forceinline__ uint64_t pack2(float lo, float hi) {
    uint64_t d;
    asm("mov.b64 %0, {%1, %2};" : "=l"(d) : "f"(lo), "f"(hi));
    return d;
}
__device__ __forceinline__ float2 unpack2(uint64_t v) {
    float lo, hi;
    asm("mov.b64 {%0, %1}, %2;" : "=f"(lo), "=f"(hi) : "l"(v));
    return make_float2(lo, hi);
}
__device__ __forceinline__ float fsig(float x) {
    return __fdividef(1.f, 1.f + __expf(-x));
}

// ---------------------------------------------------------------------------
// Phase 1: xp = x @ Wih^T + bih  (per group; 64-row x 64-col tiles, f32x2)
// grid = (500, 8, 3), block = 256
// ---------------------------------------------------------------------------
__global__ void __launch_bounds__(256) xproj_kernel(const float* __restrict__ x,
                                                    const float* __restrict__ Wih,
                                                    const float* __restrict__ bih)
{
    __shared__ __align__(16) float xs[64][68];  // [k][row]
    __shared__ __align__(16) float ws[64][68];  // [k][col]

    const int tile = blockIdx.x;
    const int g    = blockIdx.y;
    const int sec  = blockIdx.z;
    const int tid  = threadIdx.x;

    // x tile transposed (vectorized LDG)
    for (int idx = tid; idx < 64 * 16; idx += 256) {
        int row = idx >> 4;
        int k4  = (idx & 15) * 4;
        int n   = tile * 64 + row;
        float4 v = *(const float4*)&x[(size_t)n * (Gn * In) + g * In + k4];
        xs[k4 + 0][row] = v.x;
        xs[k4 + 1][row] = v.y;
        xs[k4 + 2][row] = v.z;
        xs[k4 + 3][row] = v.w;
    }
    // Wih section transposed
    for (int idx = tid; idx < 64 * 16; idx += 256) {
        int j  = idx >> 4;
        int k4 = (idx & 15) * 4;
        float4 v = *(const float4*)&Wih[((size_t)g * 192 + sec * 64 + j) * In + k4];
        ws[k4 + 0][j] = v.x;
        ws[k4 + 1][j] = v.y;
        ws[k4 + 2][j] = v.z;
        ws[k4 + 3][j] = v.w;
    }
    __syncthreads();

    const int tx = tid & 15;
    const int ty = tid >> 4;
    const int r0 = ty * 4;
    const int c0 = tx * 4;

    uint64_t A01[4], A23[4];
#pragma unroll
    for (int i = 0; i < 4; i++) { A01[i] = 0ull; A23[i] = 0ull; }

#pragma unroll 8
    for (int k = 0; k < 64; k++) {
        float4 av = *(const float4*)&xs[k][r0];
        ulonglong2 wv = *(const ulonglong2*)&ws[k][c0];
        uint64_t a0 = pack2(av.x, av.x);
        uint64_t a1 = pack2(av.y, av.y);
        uint64_t a2 = pack2(av.z, av.z);
        uint64_t a3 = pack2(av.w, av.w);
        A01[0] = ffma2(a0, wv.x, A01[0]);  A23[0] = ffma2(a0, wv.y, A23[0]);
        A01[1] = ffma2(a1, wv.x, A01[1]);  A23[1] = ffma2(a1, wv.y, A23[1]);
        A01[2] = ffma2(a2, wv.x, A01[2]);  A23[2] = ffma2(a2, wv.y, A23[2]);
        A01[3] = ffma2(a3, wv.x, A01[3]);  A23[3] = ffma2(a3, wv.y, A23[3]);
    }

    float4 bv = *(const float4*)&bih[g * 192 + sec * 64 + c0];
#pragma unroll
    for (int i = 0; i < 4; i++) {
        int n = tile * 64 + r0 + i;
        int b = n / Tn;
        int t = n - b * Tn;
        size_t o = ((size_t)(b * Gn + g) * Tn + t) * 192 + sec * 64 + c0;
        float2 lo = unpack2(A01[i]);
        float2 hi = unpack2(A23[i]);
        float4 v;
        v.x = lo.x + bv.x;
        v.y = lo.y + bv.y;
        v.z = hi.x + bv.z;
        v.w = hi.y + bv.w;
        *(float4*)&g_xp[o] = v;
    }
}

// ---------------------------------------------------------------------------
// Phase 2: sequential scan. One block per (b, g). 192 threads: thread j owns
// gate-row j of Whh (packed f32x2 in registers). h in smem.
// grid = (32, 8), block = 192
// ---------------------------------------------------------------------------
__global__ void __launch_bounds__(192) scan_kernel(const float* __restrict__ h0,
                                                   const float* __restrict__ Whh,
                                                   const float* __restrict__ bhh,
                                                   float* __restrict__ out)
{
    const int b = blockIdx.x;
    const int g = blockIdx.y;
    const int j = threadIdx.x;

    __shared__ __align__(16) float h_sh[64];
    __shared__ __align__(16) float gh_sh[192];
    __shared__ __align__(16) float xq_sh[192];

    // Whh row j as 16 x (2 packed f32x2) directly from global (pairs are contiguous)
    ulonglong2 w[16];
    const ulonglong2* wrow = (const ulonglong2*)&Whh[((size_t)g * 192 + j) * Hn];
#pragma unroll
    for (int q = 0; q < 16; q++) w[q] = wrow[q];
    const float bj = bhh[g * 192 + j];

    if (j < 64) h_sh[j] = h0[((size_t)g * Bn + b) * Hn + j];

    const float* xcol = &g_xp[((size_t)(b * Gn + g) * Tn) * 192 + j];
    float* out_row = out + (size_t)b * Tn * (Gn * Hn) + g * Hn;

#define STEP(T_, XV_)                                                         \
    {                                                                         \
        __syncthreads();                                                      \
        uint64_t A0 = pack2(bj, 0.f), A1 = 0ull, A2 = 0ull, A3 = 0ull;        \
        const ulonglong2* h2 = (const ulonglong2*)h_sh;                       \
        _Pragma("unroll")                                                     \
        for (int q = 0; q < 16; q += 2) {                                     \
            ulonglong2 ha = h2[q];                                            \
            ulonglong2 hb = h2[q + 1];                                        \
            A0 = ffma2(w[q].x,     ha.x, A0);                                 \
            A1 = ffma2(w[q].y,     ha.y, A1);                                 \
            A2 = ffma2(w[q + 1].x, hb.x, A2);                                 \
            A3 = ffma2(w[q + 1].y, hb.y, A3);                                 \
        }                                                                     \
        float2 s_ = unpack2(fadd2(fadd2(A0, A1), fadd2(A2, A3)));             \
        gh_sh[j] = s_.x + s_.y;                                               \
        xq_sh[j] = XV_;                                                       \
        __syncthreads();                                                      \
        if (j < 64) {                                                         \
            float hprev = h_sh[j];                                            \
            float rr = fsig(xq_sh[j]      + gh_sh[j]);                        \
            float zz = fsig(xq_sh[64 + j] + gh_sh[64 + j]);                   \
            float aa = xq_sh[128 + j] + rr * gh_sh[128 + j];                  \
            float nn = __fmaf_rn(2.f, fsig(2.f * aa), -1.f);                  \
            float hn = nn + zz * (hprev - nn);                                \
            h_sh[j] = hn;                                                     \
            out_row[(size_t)(T_) * (Gn * Hn) + j] = hn;                       \
        }                                                                     \
    }

    // 4-deep register prefetch ring (loop unrolled x4 -> static ring indices)
    float p0 = xcol[0];
    float p1 = xcol[192];
    float p2 = xcol[2 * 192];
    float p3 = xcol[3 * 192];

    for (int t = 0; t < Tn; t += 4) {
        STEP(t, p0);
        { int tp = min(t + 4, Tn - 1); p0 = xcol[(size_t)tp * 192]; }
        STEP(t + 1, p1);
        { int tp = min(t + 5, Tn - 1); p1 = xcol[(size_t)tp * 192]; }
        STEP(t + 2, p2);
        { int tp = min(t + 6, Tn - 1); p2 = xcol[(size_t)tp * 192]; }
        STEP(t + 3, p3);
        { int tp = min(t + 7, Tn - 1); p3 = xcol[(size_t)tp * 192]; }
    }
#undef STEP

    __syncthreads();
    if (j < 64) {
        out[(size_t)Bn * Tn * (Gn * Hn) + ((size_t)g * Bn + b) * Hn + j] = h_sh[j];
    }
}

// ---------------------------------------------------------------------------
extern "C" void kernel_launch(void* const* d_in, const int* in_sizes, int n_in,
                              void* d_out, int out_size)
{
    const float* x   = (const float*)d_in[0];
    const float* h0  = (const float*)d_in[1];
    const float* Wih = (const float*)d_in[2];
    const float* Whh = (const float*)d_in[3];
    const float* bih = (const float*)d_in[4];
    const float* bhh = (const float*)d_in[5];
    float* out = (float*)d_out;

    dim3 g1(ROWS / 64, Gn, 3);
    xproj_kernel<<<g1, 256>>>(x, Wih, bih);

    dim3 g2(Bn, Gn);
    scan_kernel<<<g2, 192>>>(h0, Whh, bhh, out);
}